// round 14
// baseline (speedup 1.0000x reference)
#include <cuda_runtime.h>
#include <cuda_bf16.h>
#include <math.h>
#include <stdint.h>

// Problem dims
#define T_ 1024
#define B_ 256
#define D_ 256
#define H_ 512
#define O_ 256

#define NBLK_A 128
#define MB 32
#define NB 32

typedef unsigned long long ull;

// bf16 hi/lo planes of hidden history, (t, b, h) layout, h contiguous
__device__ unsigned short g_Hhi[(size_t)T_ * B_ * H_];
__device__ unsigned short g_Hlo[(size_t)T_ * B_ * H_];
__device__ unsigned short g_h0hi[B_ * H_];
__device__ unsigned short g_h0lo[B_ * H_];
__device__ unsigned short g_Vhi[O_ * H_];
__device__ unsigned short g_Vlo[O_ * H_];
__device__ float          g_Ut[D_ * H_];      // U transposed (D, H)

// Per-(rowCTA, colgroup) producer flags, one cache line each. Counts warp
// arrivals: after step t, flag == 8*(t+1). Reset to 0 at tail -> replay-safe.
__device__ unsigned g_flag[16 * 8 * 32];
// Gen-based group barrier for the tail cleanup (monotone across replays)
__device__ unsigned g_cg_cnt[8 * 32];
__device__ unsigned g_cg_gen[8 * 32];

// ---------------- helpers ----------------
__device__ __forceinline__ float bf16hl(unsigned short u) {
    return __uint_as_float((unsigned)u << 16);
}
__device__ __forceinline__ unsigned smem_u32(const void* p) {
    return (unsigned)__cvta_generic_to_shared(p);
}
__device__ __forceinline__ void cp16(unsigned dst, const void* src) {
    asm volatile("cp.async.cg.shared.global [%0], [%1], 16;\n" ::"r"(dst), "l"(src));
}
__device__ __forceinline__ void cp_commit() {
    asm volatile("cp.async.commit_group;\n");
}
template <int N> __device__ __forceinline__ void cp_wait() {
    asm volatile("cp.async.wait_group %0;\n" ::"n"(N));
}
__device__ __forceinline__ float fast_tanh(float x) {
    float e, r;
    asm("ex2.approx.f32 %0, %1;" : "=f"(e) : "f"(x * 2.8853900817779268f));
    asm("rcp.approx.f32 %0, %1;" : "=f"(r) : "f"(e + 1.0f));
    return fmaf(-2.0f, r, 1.0f);
}
__device__ __forceinline__ void ldsm_x4(unsigned* r, unsigned addr) {
    asm volatile("ldmatrix.sync.aligned.m8n8.x4.shared.b16 {%0,%1,%2,%3}, [%4];"
                 : "=r"(r[0]), "=r"(r[1]), "=r"(r[2]), "=r"(r[3]) : "r"(addr));
}
__device__ __forceinline__ void ldsm_x2(unsigned* r, unsigned addr) {
    asm volatile("ldmatrix.sync.aligned.m8n8.x2.shared.b16 {%0,%1}, [%2];"
                 : "=r"(r[0]), "=r"(r[1]) : "r"(addr));
}
__device__ __forceinline__ void mma_bf16(float* d, const unsigned* a, const unsigned* b) {
    asm volatile(
        "mma.sync.aligned.m16n8k16.row.col.f32.bf16.bf16.f32 "
        "{%0,%1,%2,%3}, {%4,%5,%6,%7}, {%8,%9}, {%0,%1,%2,%3};"
        : "+f"(d[0]), "+f"(d[1]), "+f"(d[2]), "+f"(d[3])
        : "r"(a[0]), "r"(a[1]), "r"(a[2]), "r"(a[3]), "r"(b[0]), "r"(b[1]));
}

// Tail-only group barrier (16 arrivals), gen-based, replay-safe.
__device__ __forceinline__ void group_barrier(int bc) {
    __syncthreads();
    if (threadIdx.x == 0) {
        unsigned* cnt = &g_cg_cnt[bc * 32];
        unsigned* gen = &g_cg_gen[bc * 32];
        unsigned my;
        asm volatile("ld.relaxed.gpu.u32 %0, [%1];" : "=r"(my) : "l"(gen) : "memory");
        unsigned old;
        asm volatile("atom.add.release.gpu.u32 %0, [%1], %2;"
                     : "=r"(old) : "l"(cnt), "r"(1u) : "memory");
        if (old == 15u) {
            asm volatile("st.relaxed.gpu.u32 [%0], %1;" :: "l"(cnt), "r"(0u) : "memory");
            asm volatile("st.release.gpu.u32 [%0], %1;" :: "l"(gen), "r"(my + 1u) : "memory");
        } else {
            unsigned g;
            do {
                asm volatile("ld.acquire.gpu.u32 %0, [%1];" : "=r"(g) : "l"(gen) : "memory");
            } while (g == my);
        }
    }
    __syncthreads();
}

// ---------------- prep kernels ----------------
__global__ void prep_Ut(const float* __restrict__ U) {
    int d = blockIdx.x, h = threadIdx.x;
    g_Ut[(size_t)d * H_ + h] = U[(size_t)h * D_ + d];
}
__global__ void prep_h0planes(const float* __restrict__ h0) {
    int b = blockIdx.x, h = threadIdx.x;
    float v = h0[(size_t)h * B_ + b];
    __nv_bfloat16 hi = __float2bfloat16_rn(v);
    __nv_bfloat16 lo = __float2bfloat16_rn(v - __bfloat162float(hi));
    g_h0hi[(size_t)b * H_ + h] = __bfloat16_as_ushort(hi);
    g_h0lo[(size_t)b * H_ + h] = __bfloat16_as_ushort(lo);
}
__global__ void prep_Vplanes(const float* __restrict__ Vm) {
    int o = blockIdx.x, h = threadIdx.x;
    float v = Vm[(size_t)o * H_ + h];
    __nv_bfloat16 hi = __float2bfloat16_rn(v);
    __nv_bfloat16 lo = __float2bfloat16_rn(v - __bfloat162float(hi));
    g_Vhi[(size_t)o * H_ + h] = __bfloat16_as_ushort(hi);
    g_Vlo[(size_t)o * H_ + h] = __bfloat16_as_ushort(lo);
}

// ---------------- Phase A: warp-MMA recurrence, per-warp flags v2 ----------
#define WH_OFF 0
#define WL_OFF 32768
#define HH_OFF 65536
#define HL_OFF 98304
#define RED_OFF 131072
#define REDSZ  (8 * 32 * 33 * 4)            // 33792 bytes per buffer
#define SMEM_A_BYTES (RED_OFF + 2 * REDSZ)  // 198656

__global__ void __launch_bounds__(256, 1)
rnn_recur_mma(const int* __restrict__ inp, const float* __restrict__ W,
              const float* __restrict__ bh)
{
    extern __shared__ char smem[];
    const unsigned sb = smem_u32(smem);

    const int tid = threadIdx.x;
    const int w   = tid >> 5;           // 8 warps, k-split 8 x 64
    const int l   = tid & 31;
    const int bid = blockIdx.x;
    const int rr  = bid >> 3;           // row-CTA index (0..15)
    const int r0  = rr * MB;
    const int bc  = bid & 7;
    const int c0  = bc * NB;

    // one-time: split W slab (32 x 512) into Wh/Wl bf16, swizzled smem
    for (int i = tid; i < MB * H_; i += 256) {
        int row = i >> 9, k = i & 511;
        float wv = W[(size_t)(r0 + row) * H_ + k];
        __nv_bfloat16 hi = __float2bfloat16_rn(wv);
        __nv_bfloat16 lo = __float2bfloat16_rn(wv - __bfloat162float(hi));
        unsigned off = (unsigned)row * 1024u +
                       ((((unsigned)k >> 3) ^ (unsigned)(row & 7)) << 4) +
                       (unsigned)(k & 7) * 2u;
        *(__nv_bfloat16*)(smem + WH_OFF + off) = hi;
        *(__nv_bfloat16*)(smem + WL_OFF + off) = lo;
    }

    // epilogue ownership: col en (0..31), rows em..em+3
    const int en = tid >> 3;
    const int em = (tid & 7) * 4;
    const float4 bhv = *(const float4*)&bh[r0 + em];
    __syncthreads();

    // ldmatrix lane geometry (warp owns 64-wide k slice)
    const int kw    = w * 64;
    const int quad  = l >> 3, li = l & 7;
    const int a_row = ((quad & 1) << 3) + li;
    const int a_kof = (quad >> 1) << 3;
    const int b_i   = l & 7;
    const int b_half = (l >> 3) & 1;

    // hoist: all W fragments into registers (loop-invariant)
    unsigned wfh[4][2][4], wfl[4][2][4];
    #pragma unroll
    for (int ks = 0; ks < 4; ++ks) {
        const int kk = kw + ks * 16;
        #pragma unroll
        for (int mt = 0; mt < 2; ++mt) {
            int row = mt * 16 + a_row;
            unsigned aoff = (unsigned)row * 1024u +
                ((((unsigned)(kk + a_kof) >> 3) ^ (unsigned)(row & 7)) << 4);
            ldsm_x4(wfh[ks][mt], sb + WH_OFF + aoff);
            ldsm_x4(wfl[ks][mt], sb + WL_OFF + aoff);
        }
    }

    // this warp's producers: row-CTAs 2w and 2w+1 of the same column group
    const unsigned* fl0 = &g_flag[((2 * w)     * 8 + bc) * 32];
    const unsigned* fl1 = &g_flag[((2 * w + 1) * 8 + bc) * 32];
    unsigned* myflag = &g_flag[(rr * 8 + bc) * 32];

    for (int t = 0; t < T_; ++t) {
        // ---- prefetch U gather BEFORE the flag wait (no h dependency)
        int x = inp[t * B_ + c0 + en];
        float4 uv = *(const float4*)&g_Ut[(size_t)x * H_ + r0 + em];

        float acc[2][4][4];
        #pragma unroll
        for (int mt = 0; mt < 2; ++mt)
            #pragma unroll
            for (int nt = 0; nt < 4; ++nt)
                #pragma unroll
                for (int q = 0; q < 4; ++q) acc[mt][nt][q] = 0.f;

        // ---- per-warp: wait for BOTH producers of this k-slice (t>0)
        if (t > 0) {
            const unsigned target = 8u * (unsigned)t;
            unsigned v0, v1;
            do {
                asm volatile("ld.acquire.gpu.u32 %0, [%1];" : "=r"(v0) : "l"(fl0) : "memory");
                asm volatile("ld.acquire.gpu.u32 %0, [%1];" : "=r"(v1) : "l"(fl1) : "memory");
            } while (v0 < target || v1 < target);
        }

        // ---- per-warp fill of own k-slice (32 batch rows x 64 k), hi+lo
        {
            const unsigned short* sHi =
                (t == 0) ? g_h0hi : g_Hhi + (size_t)(t - 1) * B_ * H_;
            const unsigned short* sLo =
                (t == 0) ? g_h0lo : g_Hlo + (size_t)(t - 1) * B_ * H_;
            #pragma unroll
            for (int j = 0; j < 8; ++j) {
                int i = l + j * 32;              // 0..255
                int row = i >> 3;
                int cc = 8 * w + (i & 7);
                unsigned d = (unsigned)row * 1024u +
                             ((unsigned)(cc ^ (row & 7)) << 4);
                size_t src = (size_t)(c0 + row) * H_ + cc * 8;
                cp16(sb + HH_OFF + d, sHi + src);
                cp16(sb + HL_OFF + d, sLo + src);
            }
            cp_commit();
        }

        cp_wait<0>();
        __syncwarp();

        // single-pass 3-term compute: Wh*hh + Wl*hh + Wh*hl
        #pragma unroll
        for (int ks = 0; ks < 4; ++ks) {
            const int kk = kw + ks * 16;
            unsigned bhh[4][2], bhl[4][2];
            #pragma unroll
            for (int nt = 0; nt < 4; ++nt) {
                int rn = nt * 8 + b_i;
                unsigned base = (unsigned)rn * 1024u +
                    ((((unsigned)(kk + b_half * 8) >> 3) ^ (unsigned)(rn & 7)) << 4);
                ldsm_x2(bhh[nt], sb + HH_OFF + base);
                ldsm_x2(bhl[nt], sb + HL_OFF + base);
            }
            #pragma unroll
            for (int mt = 0; mt < 2; ++mt)
                #pragma unroll
                for (int nt = 0; nt < 4; ++nt) {
                    mma_bf16(acc[mt][nt], wfh[ks][mt], bhh[nt]);
                    mma_bf16(acc[mt][nt], wfl[ks][mt], bhh[nt]);
                    mma_bf16(acc[mt][nt], wfh[ks][mt], bhl[nt]);
                }
        }

        // cross-warp k reduction, double-buffered by step parity
        float* RED = (float*)(smem + RED_OFF + (t & 1) * REDSZ);
        {
            int g = l >> 2, q = l & 3;
            #pragma unroll
            for (int mt = 0; mt < 2; ++mt)
                #pragma unroll
                for (int nt = 0; nt < 4; ++nt) {
                    int m = mt * 16 + g, n = nt * 8 + 2 * q;
                    RED[(w * 32 + m) * 33 + n]         = acc[mt][nt][0];
                    RED[(w * 32 + m) * 33 + n + 1]     = acc[mt][nt][1];
                    RED[(w * 32 + m + 8) * 33 + n]     = acc[mt][nt][2];
                    RED[(w * 32 + m + 8) * 33 + n + 1] = acc[mt][nt][3];
                }
        }
        __syncthreads();     // the only block sync per step

        // epilogue: sum 8 partials + U + bias, tanh, store planes
        unsigned short* pHi = g_Hhi + (size_t)t * B_ * H_;
        unsigned short* pLo = g_Hlo + (size_t)t * B_ * H_;
        unsigned short hu[4], lu[4];
        const float* uvp = &uv.x;
        const float* bhp = &bhv.x;
        #pragma unroll
        for (int r = 0; r < 4; ++r) {
            int m = em + r;
            float s = 0.f;
            #pragma unroll
            for (int ww = 0; ww < 8; ++ww)
                s += RED[(ww * 32 + m) * 33 + en];
            float hv = fast_tanh(s + uvp[r] + bhp[r]);
            __nv_bfloat16 hi = __float2bfloat16_rn(hv);
            __nv_bfloat16 lo = __float2bfloat16_rn(hv - __bfloat162float(hi));
            hu[r] = __bfloat16_as_ushort(hi);
            lu[r] = __bfloat16_as_ushort(lo);
        }
        size_t ofs = (size_t)(c0 + en) * H_ + r0 + em;
        *(uint2*)&pHi[ofs] = *(uint2*)&hu[0];
        *(uint2*)&pLo[ofs] = *(uint2*)&lu[0];

        // per-warp publish: syncwarp orders lanes' STGs before lane0's release
        __syncwarp();
        if (l == 0) {
            unsigned old;
            asm volatile("atom.add.release.gpu.u32 %0, [%1], %2;"
                         : "=r"(old) : "l"(myflag), "r"(1u) : "memory");
        }
    }

    // tail: ensure all consumers in this column group are done, reset flag
    group_barrier(bc);
    if (tid == 0)
        asm volatile("st.relaxed.gpu.u32 [%0], %1;" :: "l"(myflag), "r"(0u) : "memory");
}

// ---------------- Phase B: tensor-core logits GEMM (proven round-8) --------
#define PB_AH 0
#define PB_AL 16384
#define PB_VH 32768
#define PB_VL 49152
#define PB_BUF 65536
#define SMEM_B_BYTES (2 * PB_BUF)

__global__ void __launch_bounds__(128, 1)
rnn_logits_mma(const float* __restrict__ by, float* __restrict__ out)
{
    extern __shared__ char smem[];
    const unsigned sb = smem_u32(smem);

    const int t  = blockIdx.z;
    const int ob = blockIdx.x * 64;
    const int bb = blockIdx.y * 64;
    const int tid = threadIdx.x;
    const int w = tid >> 5;
    const int l = tid & 31;
    const int wb = (w >> 1) * 32;
    const int wo = (w & 1) * 32;

    const int quad  = l >> 3, li = l & 7;
    const int a_row = ((quad & 1) << 3) + li;
    const int a_kof = (quad >> 1) << 3;
    const int b_i   = l & 7;
    const int b_half = (l >> 3) & 1;

    const unsigned short* Ahi = g_Hhi + ((size_t)t * B_ + bb) * H_;
    const unsigned short* Alo = g_Hlo + ((size_t)t * B_ + bb) * H_;

    auto fill = [&](int c, unsigned buf) {
        const int kc = c * 128;
        #pragma unroll
        for (int j = 0; j < 8; ++j) {
            int i = tid + j * 128;
            int row = i >> 4, cc = i & 15;
            unsigned dst = (unsigned)(row * 256) + ((unsigned)(cc ^ (row & 7)) << 4);
            size_t srcA = (size_t)row * H_ + kc + cc * 8;
            cp16(sb + buf + PB_AH + dst, Ahi + srcA);
            cp16(sb + buf + PB_AL + dst, Alo + srcA);
            size_t srcV = (size_t)(ob + row) * H_ + kc + cc * 8;
            cp16(sb + buf + PB_VH + dst, g_Vhi + srcV);
            cp16(sb + buf + PB_VL + dst, g_Vlo + srcV);
        }
    };

    float acc[2][4][4];
    #pragma unroll
    for (int mt = 0; mt < 2; ++mt)
        #pragma unroll
        for (int nt = 0; nt < 4; ++nt)
            #pragma unroll
            for (int q = 0; q < 4; ++q) acc[mt][nt][q] = 0.f;

    fill(0, 0);
    cp_commit();

    for (int c = 0; c < 4; ++c) {
        if (c < 3) fill(c + 1, (unsigned)((c + 1) & 1) * PB_BUF);
        cp_commit();
        cp_wait<1>();
        __syncthreads();

        const unsigned buf = sb + (unsigned)(c & 1) * PB_BUF;
        #pragma unroll
        for (int ks = 0; ks < 8; ++ks) {
            const int kk = ks * 16;
            unsigned vh[4][2], vl[4][2];
            #pragma unroll
            for (int nt = 0; nt < 4; ++nt) {
                int rn = wo + nt * 8 + b_i;
                unsigned boff = (unsigned)(rn * 256) +
                    ((((unsigned)(kk + b_half * 8) >> 3) ^ (unsigned)(rn & 7)) << 4);
                ldsm_x2(vh[nt], buf + PB_VH + boff);
                ldsm_x2(vl[nt], buf + PB_VL + boff);
            }
            #pragma unroll
            for (int mt = 0; mt < 2; ++mt) {
                int row = wb + mt * 16 + a_row;
                unsigned aoff = (unsigned)(row * 256) +
                    ((((unsigned)(kk + a_kof) >> 3) ^ (unsigned)(row & 7)) << 4);
                unsigned ah[4], al[4];
                ldsm_x4(ah, buf + PB_AH + aoff);
                ldsm_x4(al, buf + PB_AL + aoff);
                #pragma unroll
                for (int nt = 0; nt < 4; ++nt) {
                    mma_bf16(acc[mt][nt], ah, vh[nt]);
                    mma_bf16(acc[mt][nt], al, vh[nt]);
                    mma_bf16(acc[mt][nt], ah, vl[nt]);
                }
            }
        }
        __syncthreads();
    }

    const int fr = l >> 2, fc = 2 * (l & 3);
    #pragma unroll
    for (int nt = 0; nt < 4; ++nt) {
        int col = ob + wo + nt * 8 + fc;
        float2 b2 = *(const float2*)&by[col];
        #pragma unroll
        for (int mt = 0; mt < 2; ++mt) {
            int r0w = bb + wb + mt * 16 + fr;
            float2 v0 = make_float2(acc[mt][nt][0] + b2.x, acc[mt][nt][1] + b2.y);
            float2 v1 = make_float2(acc[mt][nt][2] + b2.x, acc[mt][nt][3] + b2.y);
            *(float2*)&out[((size_t)t * B_ + r0w) * O_ + col]     = v0;
            *(float2*)&out[((size_t)t * B_ + r0w + 8) * O_ + col] = v1;
        }
    }
}

// Optional hT (H,B) appended after logits: reconstruct from planes
__global__ void copy_hT_kernel(float* __restrict__ out) {
    int h = blockIdx.x;
    int b = threadIdx.x;
    size_t ofs = (size_t)(T_ - 1) * B_ * H_ + (size_t)b * H_ + h;
    out[(size_t)h * B_ + b] = bf16hl(g_Hhi[ofs]) + bf16hl(g_Hlo[ofs]);
}

extern "C" void kernel_launch(void* const* d_in, const int* in_sizes, int n_in,
                              void* d_out, int out_size) {
    const int*   inp = (const int*)d_in[0];
    const float* h0  = (const float*)d_in[1];
    const float* U   = (const float*)d_in[2];
    const float* W   = (const float*)d_in[3];
    const float* Vm  = (const float*)d_in[4];
    const float* bh  = (const float*)d_in[5];
    const float* by  = (const float*)d_in[6];
    float* out = (float*)d_out;

    cudaFuncSetAttribute(rnn_recur_mma,
                         cudaFuncAttributeMaxDynamicSharedMemorySize,
                         (int)SMEM_A_BYTES);
    cudaFuncSetAttribute(rnn_logits_mma,
                         cudaFuncAttributeMaxDynamicSharedMemorySize,
                         (int)SMEM_B_BYTES);

    prep_Ut<<<D_, H_>>>(U);
    prep_h0planes<<<B_, H_>>>(h0);
    prep_Vplanes<<<O_, H_>>>(Vm);

    rnn_recur_mma<<<NBLK_A, 256, SMEM_A_BYTES>>>(inp, W, bh);

    dim3 gridB(O_ / 64, B_ / 64, T_);
    rnn_logits_mma<<<gridB, 128, SMEM_B_BYTES>>>(by, out);

    if (out_size >= T_ * B_ * O_ + H_ * B_) {
        copy_hT_kernel<<<H_, B_>>>(out + (size_t)T_ * B_ * O_);
    }
}

// round 15
// speedup vs baseline: 1.0769x; 1.0769x over previous
#include <cuda_runtime.h>
#include <cuda_bf16.h>
#include <math.h>
#include <stdint.h>

// Problem dims
#define T_ 1024
#define B_ 256
#define D_ 256
#define H_ 512
#define O_ 256

#define NBLK_A 128
#define MB 32
#define NB 32

typedef unsigned long long ull;

// bf16 hi/lo planes of hidden history, (t, b, h) layout, h contiguous
__device__ unsigned short g_Hhi[(size_t)T_ * B_ * H_];
__device__ unsigned short g_Hlo[(size_t)T_ * B_ * H_];
__device__ unsigned short g_h0hi[B_ * H_];
__device__ unsigned short g_h0lo[B_ * H_];
__device__ unsigned short g_Vhi[O_ * H_];
__device__ unsigned short g_Vlo[O_ * H_];
__device__ float          g_Ut[D_ * H_];      // U transposed (D, H)

// Per-(rowCTA, colgroup) producer flags, one cache line each. Single writer
// (tid0 of the owning CTA); value = t+1 after step t. Reset at tail.
__device__ unsigned g_flag[16 * 8 * 32];
// Gen-based group barrier for the tail cleanup (monotone across replays)
__device__ unsigned g_cg_cnt[8 * 32];
__device__ unsigned g_cg_gen[8 * 32];

// ---------------- helpers ----------------
__device__ __forceinline__ float bf16hl(unsigned short u) {
    return __uint_as_float((unsigned)u << 16);
}
__device__ __forceinline__ unsigned smem_u32(const void* p) {
    return (unsigned)__cvta_generic_to_shared(p);
}
__device__ __forceinline__ void cp16(unsigned dst, const void* src) {
    asm volatile("cp.async.cg.shared.global [%0], [%1], 16;\n" ::"r"(dst), "l"(src));
}
__device__ __forceinline__ void cp_commit() {
    asm volatile("cp.async.commit_group;\n");
}
template <int N> __device__ __forceinline__ void cp_wait() {
    asm volatile("cp.async.wait_group %0;\n" ::"n"(N));
}
__device__ __forceinline__ float fast_tanh(float x) {
    float e, r;
    asm("ex2.approx.f32 %0, %1;" : "=f"(e) : "f"(x * 2.8853900817779268f));
    asm("rcp.approx.f32 %0, %1;" : "=f"(r) : "f"(e + 1.0f));
    return fmaf(-2.0f, r, 1.0f);
}
__device__ __forceinline__ void ldsm_x4(unsigned* r, unsigned addr) {
    asm volatile("ldmatrix.sync.aligned.m8n8.x4.shared.b16 {%0,%1,%2,%3}, [%4];"
                 : "=r"(r[0]), "=r"(r[1]), "=r"(r[2]), "=r"(r[3]) : "r"(addr));
}
__device__ __forceinline__ void ldsm_x2(unsigned* r, unsigned addr) {
    asm volatile("ldmatrix.sync.aligned.m8n8.x2.shared.b16 {%0,%1}, [%2];"
                 : "=r"(r[0]), "=r"(r[1]) : "r"(addr));
}
__device__ __forceinline__ void mma_bf16(float* d, const unsigned* a, const unsigned* b) {
    asm volatile(
        "mma.sync.aligned.m16n8k16.row.col.f32.bf16.bf16.f32 "
        "{%0,%1,%2,%3}, {%4,%5,%6,%7}, {%8,%9}, {%0,%1,%2,%3};"
        : "+f"(d[0]), "+f"(d[1]), "+f"(d[2]), "+f"(d[3])
        : "r"(a[0]), "r"(a[1]), "r"(a[2]), "r"(a[3]), "r"(b[0]), "r"(b[1]));
}

// Tail-only group barrier (16 arrivals), gen-based, replay-safe.
__device__ __forceinline__ void group_barrier(int bc) {
    __syncthreads();
    if (threadIdx.x == 0) {
        unsigned* cnt = &g_cg_cnt[bc * 32];
        unsigned* gen = &g_cg_gen[bc * 32];
        unsigned my;
        asm volatile("ld.relaxed.gpu.u32 %0, [%1];" : "=r"(my) : "l"(gen) : "memory");
        unsigned old;
        asm volatile("atom.add.release.gpu.u32 %0, [%1], %2;"
                     : "=r"(old) : "l"(cnt), "r"(1u) : "memory");
        if (old == 15u) {
            asm volatile("st.relaxed.gpu.u32 [%0], %1;" :: "l"(cnt), "r"(0u) : "memory");
            asm volatile("st.release.gpu.u32 [%0], %1;" :: "l"(gen), "r"(my + 1u) : "memory");
        } else {
            unsigned g;
            do {
                asm volatile("ld.acquire.gpu.u32 %0, [%1];" : "=r"(g) : "l"(gen) : "memory");
            } while (g == my);
        }
    }
    __syncthreads();
}

// ---------------- prep kernels ----------------
__global__ void prep_Ut(const float* __restrict__ U) {
    int d = blockIdx.x, h = threadIdx.x;
    g_Ut[(size_t)d * H_ + h] = U[(size_t)h * D_ + d];
}
__global__ void prep_h0planes(const float* __restrict__ h0) {
    int b = blockIdx.x, h = threadIdx.x;
    float v = h0[(size_t)h * B_ + b];
    __nv_bfloat16 hi = __float2bfloat16_rn(v);
    __nv_bfloat16 lo = __float2bfloat16_rn(v - __bfloat162float(hi));
    g_h0hi[(size_t)b * H_ + h] = __bfloat16_as_ushort(hi);
    g_h0lo[(size_t)b * H_ + h] = __bfloat16_as_ushort(lo);
}
__global__ void prep_Vplanes(const float* __restrict__ Vm) {
    int o = blockIdx.x, h = threadIdx.x;
    float v = Vm[(size_t)o * H_ + h];
    __nv_bfloat16 hi = __float2bfloat16_rn(v);
    __nv_bfloat16 lo = __float2bfloat16_rn(v - __bfloat162float(hi));
    g_Vhi[(size_t)o * H_ + h] = __bfloat16_as_ushort(hi);
    g_Vlo[(size_t)o * H_ + h] = __bfloat16_as_ushort(lo);
}

// ---------------- Phase A: warp-MMA recurrence (round-13 + safe deltas) ----
#define WH_OFF 0
#define WL_OFF 32768
#define HH_OFF 65536
#define HL_OFF 98304
#define RED_OFF 131072
#define SMEM_A_BYTES (RED_OFF + 8 * 32 * 33 * 4)

__global__ void __launch_bounds__(256, 1)
rnn_recur_mma(const int* __restrict__ inp, const float* __restrict__ W,
              const float* __restrict__ bh)
{
    extern __shared__ char smem[];
    const unsigned sb = smem_u32(smem);
    float* RED = (float*)(smem + RED_OFF);

    const int tid = threadIdx.x;
    const int w   = tid >> 5;           // 8 warps, k-split 8 x 64
    const int l   = tid & 31;
    const int bid = blockIdx.x;
    const int rr  = bid >> 3;           // row-CTA index (0..15)
    const int r0  = rr * MB;
    const int bc  = bid & 7;
    const int c0  = bc * NB;

    // one-time: split W slab (32 x 512) into Wh/Wl bf16, swizzled smem
    for (int i = tid; i < MB * H_; i += 256) {
        int row = i >> 9, k = i & 511;
        float wv = W[(size_t)(r0 + row) * H_ + k];
        __nv_bfloat16 hi = __float2bfloat16_rn(wv);
        __nv_bfloat16 lo = __float2bfloat16_rn(wv - __bfloat162float(hi));
        unsigned off = (unsigned)row * 1024u +
                       ((((unsigned)k >> 3) ^ (unsigned)(row & 7)) << 4) +
                       (unsigned)(k & 7) * 2u;
        *(__nv_bfloat16*)(smem + WH_OFF + off) = hi;
        *(__nv_bfloat16*)(smem + WL_OFF + off) = lo;
    }

    // epilogue ownership: col en (0..31), rows em..em+3
    const int en = tid >> 3;
    const int em = (tid & 7) * 4;
    const float4 bhv = *(const float4*)&bh[r0 + em];
    __syncthreads();

    // ldmatrix lane geometry (warp owns 64-wide k slice)
    const int kw    = w * 64;
    const int quad  = l >> 3, li = l & 7;
    const int a_row = ((quad & 1) << 3) + li;
    const int a_kof = (quad >> 1) << 3;
    const int b_i   = l & 7;
    const int b_half = (l >> 3) & 1;

    // hoist: all W fragments into registers (loop-invariant)
    unsigned wfh[4][2][4], wfl[4][2][4];
    #pragma unroll
    for (int ks = 0; ks < 4; ++ks) {
        const int kk = kw + ks * 16;
        #pragma unroll
        for (int mt = 0; mt < 2; ++mt) {
            int row = mt * 16 + a_row;
            unsigned aoff = (unsigned)row * 1024u +
                ((((unsigned)(kk + a_kof) >> 3) ^ (unsigned)(row & 7)) << 4);
            ldsm_x4(wfh[ks][mt], sb + WH_OFF + aoff);
            ldsm_x4(wfl[ks][mt], sb + WL_OFF + aoff);
        }
    }

    // this warp's producers: row-CTAs 2w and 2w+1 of the same column group
    const unsigned* fl0 = &g_flag[((2 * w)     * 8 + bc) * 32];
    const unsigned* fl1 = &g_flag[((2 * w + 1) * 8 + bc) * 32];
    unsigned* myflag = &g_flag[(rr * 8 + bc) * 32];

    for (int t = 0; t < T_; ++t) {
        // ---- prefetch U gather BEFORE the flag wait (no h dependency)
        int x = inp[t * B_ + c0 + en];
        float4 uv = *(const float4*)&g_Ut[(size_t)x * H_ + r0 + em];

        float acc[2][4][4];
        #pragma unroll
        for (int mt = 0; mt < 2; ++mt)
            #pragma unroll
            for (int nt = 0; nt < 4; ++nt)
                #pragma unroll
                for (int q = 0; q < 4; ++q) acc[mt][nt][q] = 0.f;

        // ---- per-warp: fused wait for BOTH producers of this k-slice (t>0)
        if (t > 0) {
            unsigned v0, v1;
            do {
                asm volatile("ld.acquire.gpu.u32 %0, [%1];" : "=r"(v0) : "l"(fl0) : "memory");
                asm volatile("ld.acquire.gpu.u32 %0, [%1];" : "=r"(v1) : "l"(fl1) : "memory");
            } while (v0 < (unsigned)t || v1 < (unsigned)t);
        }

        // ---- per-warp fill of own k-slice (32 batch rows x 64 k), hi+lo
        {
            const unsigned short* sHi =
                (t == 0) ? g_h0hi : g_Hhi + (size_t)(t - 1) * B_ * H_;
            const unsigned short* sLo =
                (t == 0) ? g_h0lo : g_Hlo + (size_t)(t - 1) * B_ * H_;
            #pragma unroll
            for (int j = 0; j < 8; ++j) {
                int i = l + j * 32;              // 0..255
                int row = i >> 3;
                int cc = 8 * w + (i & 7);
                unsigned d = (unsigned)row * 1024u +
                             ((unsigned)(cc ^ (row & 7)) << 4);
                size_t src = (size_t)(c0 + row) * H_ + cc * 8;
                cp16(sb + HH_OFF + d, sHi + src);
                cp16(sb + HL_OFF + d, sLo + src);
            }
            cp_commit();
        }

        cp_wait<0>();
        __syncwarp();

        // single-pass 3-term compute: Wh*hh + Wl*hh + Wh*hl
        #pragma unroll
        for (int ks = 0; ks < 4; ++ks) {
            const int kk = kw + ks * 16;
            unsigned bhh[4][2], bhl[4][2];
            #pragma unroll
            for (int nt = 0; nt < 4; ++nt) {
                int rn = nt * 8 + b_i;
                unsigned base = (unsigned)rn * 1024u +
                    ((((unsigned)(kk + b_half * 8) >> 3) ^ (unsigned)(rn & 7)) << 4);
                ldsm_x2(bhh[nt], sb + HH_OFF + base);
                ldsm_x2(bhl[nt], sb + HL_OFF + base);
            }
            #pragma unroll
            for (int mt = 0; mt < 2; ++mt)
                #pragma unroll
                for (int nt = 0; nt < 4; ++nt) {
                    mma_bf16(acc[mt][nt], wfh[ks][mt], bhh[nt]);
                    mma_bf16(acc[mt][nt], wfl[ks][mt], bhh[nt]);
                    mma_bf16(acc[mt][nt], wfh[ks][mt], bhl[nt]);
                }
        }

        // cross-warp k reduction (8 partials)
        {
            int g = l >> 2, q = l & 3;
            #pragma unroll
            for (int mt = 0; mt < 2; ++mt)
                #pragma unroll
                for (int nt = 0; nt < 4; ++nt) {
                    int m = mt * 16 + g, n = nt * 8 + 2 * q;
                    RED[(w * 32 + m) * 33 + n]         = acc[mt][nt][0];
                    RED[(w * 32 + m) * 33 + n + 1]     = acc[mt][nt][1];
                    RED[(w * 32 + m + 8) * 33 + n]     = acc[mt][nt][2];
                    RED[(w * 32 + m + 8) * 33 + n + 1] = acc[mt][nt][3];
                }
        }
        __syncthreads();

        // epilogue: sum 8 partials + U + bias, tanh, store planes
        unsigned short* pHi = g_Hhi + (size_t)t * B_ * H_;
        unsigned short* pLo = g_Hlo + (size_t)t * B_ * H_;
        unsigned short hu[4], lu[4];
        const float* uvp = &uv.x;
        const float* bhp = &bhv.x;
        #pragma unroll
        for (int r = 0; r < 4; ++r) {
            int m = em + r;
            float s = 0.f;
            #pragma unroll
            for (int ww = 0; ww < 8; ++ww)
                s += RED[(ww * 32 + m) * 33 + en];
            float hv = fast_tanh(s + uvp[r] + bhp[r]);
            __nv_bfloat16 hi = __float2bfloat16_rn(hv);
            __nv_bfloat16 lo = __float2bfloat16_rn(hv - __bfloat162float(hi));
            hu[r] = __bfloat16_as_ushort(hi);
            lu[r] = __bfloat16_as_ushort(lo);
        }
        size_t ofs = (size_t)(c0 + en) * H_ + r0 + em;
        *(uint2*)&pHi[ofs] = *(uint2*)&hu[0];
        *(uint2*)&pLo[ofs] = *(uint2*)&lu[0];

        __syncthreads();
        // publish h_t: single-writer release store (flag := t+1)
        if (tid == 0) {
            asm volatile("st.release.gpu.u32 [%0], %1;"
                         :: "l"(myflag), "r"((unsigned)(t + 1)) : "memory");
        }
    }

    // tail: ensure all consumers in this column group are done, reset flag
    group_barrier(bc);
    if (tid == 0)
        asm volatile("st.relaxed.gpu.u32 [%0], %1;" :: "l"(myflag), "r"(0u) : "memory");
}

// ---------------- Phase B: tensor-core logits GEMM (proven round-8) --------
#define PB_AH 0
#define PB_AL 16384
#define PB_VH 32768
#define PB_VL 49152
#define PB_BUF 65536
#define SMEM_B_BYTES (2 * PB_BUF)

__global__ void __launch_bounds__(128, 1)
rnn_logits_mma(const float* __restrict__ by, float* __restrict__ out)
{
    extern __shared__ char smem[];
    const unsigned sb = smem_u32(smem);

    const int t  = blockIdx.z;
    const int ob = blockIdx.x * 64;
    const int bb = blockIdx.y * 64;
    const int tid = threadIdx.x;
    const int w = tid >> 5;
    const int l = tid & 31;
    const int wb = (w >> 1) * 32;
    const int wo = (w & 1) * 32;

    const int quad  = l >> 3, li = l & 7;
    const int a_row = ((quad & 1) << 3) + li;
    const int a_kof = (quad >> 1) << 3;
    const int b_i   = l & 7;
    const int b_half = (l >> 3) & 1;

    const unsigned short* Ahi = g_Hhi + ((size_t)t * B_ + bb) * H_;
    const unsigned short* Alo = g_Hlo + ((size_t)t * B_ + bb) * H_;

    auto fill = [&](int c, unsigned buf) {
        const int kc = c * 128;
        #pragma unroll
        for (int j = 0; j < 8; ++j) {
            int i = tid + j * 128;
            int row = i >> 4, cc = i & 15;
            unsigned dst = (unsigned)(row * 256) + ((unsigned)(cc ^ (row & 7)) << 4);
            size_t srcA = (size_t)row * H_ + kc + cc * 8;
            cp16(sb + buf + PB_AH + dst, Ahi + srcA);
            cp16(sb + buf + PB_AL + dst, Alo + srcA);
            size_t srcV = (size_t)(ob + row) * H_ + kc + cc * 8;
            cp16(sb + buf + PB_VH + dst, g_Vhi + srcV);
            cp16(sb + buf + PB_VL + dst, g_Vlo + srcV);
        }
    };

    float acc[2][4][4];
    #pragma unroll
    for (int mt = 0; mt < 2; ++mt)
        #pragma unroll
        for (int nt = 0; nt < 4; ++nt)
            #pragma unroll
            for (int q = 0; q < 4; ++q) acc[mt][nt][q] = 0.f;

    fill(0, 0);
    cp_commit();

    for (int c = 0; c < 4; ++c) {
        if (c < 3) fill(c + 1, (unsigned)((c + 1) & 1) * PB_BUF);
        cp_commit();
        cp_wait<1>();
        __syncthreads();

        const unsigned buf = sb + (unsigned)(c & 1) * PB_BUF;
        #pragma unroll
        for (int ks = 0; ks < 8; ++ks) {
            const int kk = ks * 16;
            unsigned vh[4][2], vl[4][2];
            #pragma unroll
            for (int nt = 0; nt < 4; ++nt) {
                int rn = wo + nt * 8 + b_i;
                unsigned boff = (unsigned)(rn * 256) +
                    ((((unsigned)(kk + b_half * 8) >> 3) ^ (unsigned)(rn & 7)) << 4);
                ldsm_x2(vh[nt], buf + PB_VH + boff);
                ldsm_x2(vl[nt], buf + PB_VL + boff);
            }
            #pragma unroll
            for (int mt = 0; mt < 2; ++mt) {
                int row = wb + mt * 16 + a_row;
                unsigned aoff = (unsigned)(row * 256) +
                    ((((unsigned)(kk + a_kof) >> 3) ^ (unsigned)(row & 7)) << 4);
                unsigned ah[4], al[4];
                ldsm_x4(ah, buf + PB_AH + aoff);
                ldsm_x4(al, buf + PB_AL + aoff);
                #pragma unroll
                for (int nt = 0; nt < 4; ++nt) {
                    mma_bf16(acc[mt][nt], ah, vh[nt]);
                    mma_bf16(acc[mt][nt], al, vh[nt]);
                    mma_bf16(acc[mt][nt], ah, vl[nt]);
                }
            }
        }
        __syncthreads();
    }

    const int fr = l >> 2, fc = 2 * (l & 3);
    #pragma unroll
    for (int nt = 0; nt < 4; ++nt) {
        int col = ob + wo + nt * 8 + fc;
        float2 b2 = *(const float2*)&by[col];
        #pragma unroll
        for (int mt = 0; mt < 2; ++mt) {
            int r0w = bb + wb + mt * 16 + fr;
            float2 v0 = make_float2(acc[mt][nt][0] + b2.x, acc[mt][nt][1] + b2.y);
            float2 v1 = make_float2(acc[mt][nt][2] + b2.x, acc[mt][nt][3] + b2.y);
            *(float2*)&out[((size_t)t * B_ + r0w) * O_ + col]     = v0;
            *(float2*)&out[((size_t)t * B_ + r0w + 8) * O_ + col] = v1;
        }
    }
}

// Optional hT (H,B) appended after logits: reconstruct from planes
__global__ void copy_hT_kernel(float* __restrict__ out) {
    int h = blockIdx.x;
    int b = threadIdx.x;
    size_t ofs = (size_t)(T_ - 1) * B_ * H_ + (size_t)b * H_ + h;
    out[(size_t)h * B_ + b] = bf16hl(g_Hhi[ofs]) + bf16hl(g_Hlo[ofs]);
}

extern "C" void kernel_launch(void* const* d_in, const int* in_sizes, int n_in,
                              void* d_out, int out_size) {
    const int*   inp = (const int*)d_in[0];
    const float* h0  = (const float*)d_in[1];
    const float* U   = (const float*)d_in[2];
    const float* W   = (const float*)d_in[3];
    const float* Vm  = (const float*)d_in[4];
    const float* bh  = (const float*)d_in[5];
    const float* by  = (const float*)d_in[6];
    float* out = (float*)d_out;

    cudaFuncSetAttribute(rnn_recur_mma,
                         cudaFuncAttributeMaxDynamicSharedMemorySize,
                         (int)SMEM_A_BYTES);
    cudaFuncSetAttribute(rnn_logits_mma,
                         cudaFuncAttributeMaxDynamicSharedMemorySize,
                         (int)SMEM_B_BYTES);

    prep_Ut<<<D_, H_>>>(U);
    prep_h0planes<<<B_, H_>>>(h0);
    prep_Vplanes<<<O_, H_>>>(Vm);

    rnn_recur_mma<<<NBLK_A, 256, SMEM_A_BYTES>>>(inp, W, bh);

    dim3 gridB(O_ / 64, B_ / 64, T_);
    rnn_logits_mma<<<gridB, 128, SMEM_B_BYTES>>>(by, out);

    if (out_size >= T_ * B_ * O_ + H_ * B_) {
        copy_hT_kernel<<<H_, B_>>>(out + (size_t)T_ * B_ * O_);
    }
}

// round 16
// speedup vs baseline: 1.1083x; 1.0292x over previous
#include <cuda_runtime.h>
#include <cuda_bf16.h>
#include <math.h>
#include <stdint.h>

// Problem dims
#define T_ 1024
#define B_ 256
#define D_ 256
#define H_ 512
#define O_ 256

#define NBLK_A 128
#define MB 32
#define NB 32

typedef unsigned long long ull;

// bf16 hi/lo planes of hidden history, (t, b, h) layout, h contiguous
__device__ unsigned short g_Hhi[(size_t)T_ * B_ * H_];
__device__ unsigned short g_Hlo[(size_t)T_ * B_ * H_];
__device__ unsigned short g_h0hi[B_ * H_];
__device__ unsigned short g_h0lo[B_ * H_];
__device__ unsigned short g_Vhi[O_ * H_];
__device__ unsigned short g_Vlo[O_ * H_];
__device__ float          g_Ut[D_ * H_];      // U transposed (D, H)

// Per-(rowCTA, colgroup) producer flags, one cache line each. Single writer;
// value = t+1 after step t. Reset at tail -> replay-safe.
__device__ unsigned g_flag[16 * 8 * 32];
// Gen-based group barrier for the tail cleanup (monotone across replays)
__device__ unsigned g_cg_cnt[8 * 32];
__device__ unsigned g_cg_gen[8 * 32];

// ---------------- helpers ----------------
__device__ __forceinline__ float bf16hl(unsigned short u) {
    return __uint_as_float((unsigned)u << 16);
}
__device__ __forceinline__ unsigned smem_u32(const void* p) {
    return (unsigned)__cvta_generic_to_shared(p);
}
__device__ __forceinline__ void cp16(unsigned dst, const void* src) {
    asm volatile("cp.async.cg.shared.global [%0], [%1], 16;\n" ::"r"(dst), "l"(src));
}
__device__ __forceinline__ void cp_commit() {
    asm volatile("cp.async.commit_group;\n");
}
template <int N> __device__ __forceinline__ void cp_wait() {
    asm volatile("cp.async.wait_group %0;\n" ::"n"(N));
}
__device__ __forceinline__ float fast_tanh(float x) {
    float e, r;
    asm("ex2.approx.f32 %0, %1;" : "=f"(e) : "f"(x * 2.8853900817779268f));
    asm("rcp.approx.f32 %0, %1;" : "=f"(r) : "f"(e + 1.0f));
    return fmaf(-2.0f, r, 1.0f);
}
__device__ __forceinline__ void ldsm_x4(unsigned* r, unsigned addr) {
    asm volatile("ldmatrix.sync.aligned.m8n8.x4.shared.b16 {%0,%1,%2,%3}, [%4];"
                 : "=r"(r[0]), "=r"(r[1]), "=r"(r[2]), "=r"(r[3]) : "r"(addr));
}
__device__ __forceinline__ void ldsm_x2(unsigned* r, unsigned addr) {
    asm volatile("ldmatrix.sync.aligned.m8n8.x2.shared.b16 {%0,%1}, [%2];"
                 : "=r"(r[0]), "=r"(r[1]) : "r"(addr));
}
__device__ __forceinline__ void mma_bf16(float* d, const unsigned* a, const unsigned* b) {
    asm volatile(
        "mma.sync.aligned.m16n8k16.row.col.f32.bf16.bf16.f32 "
        "{%0,%1,%2,%3}, {%4,%5,%6,%7}, {%8,%9}, {%0,%1,%2,%3};"
        : "+f"(d[0]), "+f"(d[1]), "+f"(d[2]), "+f"(d[3])
        : "r"(a[0]), "r"(a[1]), "r"(a[2]), "r"(a[3]), "r"(b[0]), "r"(b[1]));
}

// Tail-only group barrier (16 arrivals), gen-based, replay-safe.
__device__ __forceinline__ void group_barrier(int bc) {
    __syncthreads();
    if (threadIdx.x == 0) {
        unsigned* cnt = &g_cg_cnt[bc * 32];
        unsigned* gen = &g_cg_gen[bc * 32];
        unsigned my;
        asm volatile("ld.relaxed.gpu.u32 %0, [%1];" : "=r"(my) : "l"(gen) : "memory");
        unsigned old;
        asm volatile("atom.add.release.gpu.u32 %0, [%1], %2;"
                     : "=r"(old) : "l"(cnt), "r"(1u) : "memory");
        if (old == 15u) {
            asm volatile("st.relaxed.gpu.u32 [%0], %1;" :: "l"(cnt), "r"(0u) : "memory");
            asm volatile("st.release.gpu.u32 [%0], %1;" :: "l"(gen), "r"(my + 1u) : "memory");
        } else {
            unsigned g;
            do {
                asm volatile("ld.acquire.gpu.u32 %0, [%1];" : "=r"(g) : "l"(gen) : "memory");
            } while (g == my);
        }
    }
    __syncthreads();
}

// ---------------- prep kernels ----------------
__global__ void prep_Ut(const float* __restrict__ U) {
    int d = blockIdx.x, h = threadIdx.x;
    g_Ut[(size_t)d * H_ + h] = U[(size_t)h * D_ + d];
}
__global__ void prep_h0planes(const float* __restrict__ h0) {
    int b = blockIdx.x, h = threadIdx.x;
    float v = h0[(size_t)h * B_ + b];
    __nv_bfloat16 hi = __float2bfloat16_rn(v);
    __nv_bfloat16 lo = __float2bfloat16_rn(v - __bfloat162float(hi));
    g_h0hi[(size_t)b * H_ + h] = __bfloat16_as_ushort(hi);
    g_h0lo[(size_t)b * H_ + h] = __bfloat16_as_ushort(lo);
}
__global__ void prep_Vplanes(const float* __restrict__ Vm) {
    int o = blockIdx.x, h = threadIdx.x;
    float v = Vm[(size_t)o * H_ + h];
    __nv_bfloat16 hi = __float2bfloat16_rn(v);
    __nv_bfloat16 lo = __float2bfloat16_rn(v - __bfloat162float(hi));
    g_Vhi[(size_t)o * H_ + h] = __bfloat16_as_ushort(hi);
    g_Vlo[(size_t)o * H_ + h] = __bfloat16_as_ushort(lo);
}

// ------- Phase A+B fused: recurrence + in-slack logits, per-warp flags -----
#define WH_OFF 0
#define WL_OFF 32768
#define HH_OFF 65536
#define HL_OFF 98304
#define RED_OFF 131072
#define REDSZ   (8 * 32 * 33 * 4)               // 33792
#define RED2_OFF (RED_OFF + REDSZ)              // 164864
#define RED2SZ  (8 * 32 * 18 * 4)               // 18432
#define SMEM_A_BYTES (RED2_OFF + RED2SZ)        // 183296

__global__ void __launch_bounds__(256, 1)
rnn_recur_mma(const int* __restrict__ inp, const float* __restrict__ W,
              const float* __restrict__ bh, const float* __restrict__ by,
              float* __restrict__ out)
{
    extern __shared__ char smem[];
    const unsigned sb = smem_u32(smem);
    float* RED  = (float*)(smem + RED_OFF);
    float* RED2 = (float*)(smem + RED2_OFF);

    const int tid = threadIdx.x;
    const int w   = tid >> 5;           // 8 warps, k-split 8 x 64
    const int l   = tid & 31;
    const int bid = blockIdx.x;
    const int rr  = bid >> 3;           // row-CTA index (0..15)
    const int r0  = rr * MB;
    const int bc  = bid & 7;
    const int c0  = bc * NB;

    // one-time: split W slab (32 x 512) into Wh/Wl bf16, swizzled smem
    for (int i = tid; i < MB * H_; i += 256) {
        int row = i >> 9, k = i & 511;
        float wv = W[(size_t)(r0 + row) * H_ + k];
        __nv_bfloat16 hi = __float2bfloat16_rn(wv);
        __nv_bfloat16 lo = __float2bfloat16_rn(wv - __bfloat162float(hi));
        unsigned off = (unsigned)row * 1024u +
                       ((((unsigned)k >> 3) ^ (unsigned)(row & 7)) << 4) +
                       (unsigned)(k & 7) * 2u;
        *(__nv_bfloat16*)(smem + WH_OFF + off) = hi;
        *(__nv_bfloat16*)(smem + WL_OFF + off) = lo;
    }

    // epilogue ownership (recurrence): col en (0..31), rows em..em+3
    const int en = tid >> 3;
    const int em = (tid & 7) * 4;
    const float4 bhv = *(const float4*)&bh[r0 + em];
    // logits epilogue ownership: batch lb (0..31), o pair lo2 (0..14 step 2)
    const int lb  = tid >> 3;
    const int lo2 = (tid & 7) * 2;
    const float2 byv2 = *(const float2*)&by[rr * 16 + lo2];

    // stage V slice (16 o-rows x 512 k, hi/lo) into RED area, swizzled
    for (int i = tid; i < 16 * 64; i += 256) {
        int row = i >> 6, c = i & 63;
        unsigned d = (unsigned)row * 1024u + ((unsigned)(c ^ (row & 7)) << 4);
        size_t src = (size_t)(rr * 16 + row) * H_ + c * 8;
        cp16(sb + RED_OFF + d,         g_Vhi + src);
        cp16(sb + RED_OFF + 16384 + d, g_Vlo + src);
    }
    cp_commit();
    cp_wait<0>();
    __syncthreads();

    // ldmatrix lane geometry (warp owns 64-wide k slice)
    const int kw    = w * 64;
    const int quad  = l >> 3, li = l & 7;
    const int a_row = ((quad & 1) << 3) + li;
    const int a_kof = (quad >> 1) << 3;
    const int b_i   = l & 7;
    const int b_half = (l >> 3) & 1;

    // hoist V fragments (B operand: 16 o-rows, own k slice) -> 32 regs
    unsigned vfh[4][2][2], vfl[4][2][2];
    #pragma unroll
    for (int ks = 0; ks < 4; ++ks) {
        const int kk = kw + ks * 16;
        #pragma unroll
        for (int nt = 0; nt < 2; ++nt) {
            int rn = nt * 8 + b_i;
            unsigned off = (unsigned)rn * 1024u +
                ((((unsigned)(kk + b_half * 8) >> 3) ^ (unsigned)(rn & 7)) << 4);
            ldsm_x2(vfh[ks][nt], sb + RED_OFF + off);
            ldsm_x2(vfl[ks][nt], sb + RED_OFF + 16384 + off);
        }
    }
    __syncthreads();   // V staging area reverts to RED scratch

    // hoist W fragments -> 64 regs
    unsigned wfh[4][2][4], wfl[4][2][4];
    #pragma unroll
    for (int ks = 0; ks < 4; ++ks) {
        const int kk = kw + ks * 16;
        #pragma unroll
        for (int mt = 0; mt < 2; ++mt) {
            int row = mt * 16 + a_row;
            unsigned aoff = (unsigned)row * 1024u +
                ((((unsigned)(kk + a_kof) >> 3) ^ (unsigned)(row & 7)) << 4);
            ldsm_x4(wfh[ks][mt], sb + WH_OFF + aoff);
            ldsm_x4(wfl[ks][mt], sb + WL_OFF + aoff);
        }
    }

    const unsigned* fl0 = &g_flag[((2 * w)     * 8 + bc) * 32];
    const unsigned* fl1 = &g_flag[((2 * w + 1) * 8 + bc) * 32];
    unsigned* myflag = &g_flag[(rr * 8 + bc) * 32];

    // ---- logits for the h currently in smem (timestep tprev), off crit path
    auto do_logits = [&](int tprev) {
        float lacc[2][2][4];
        #pragma unroll
        for (int mt = 0; mt < 2; ++mt)
            #pragma unroll
            for (int nt = 0; nt < 2; ++nt)
                #pragma unroll
                for (int q = 0; q < 4; ++q) lacc[mt][nt][q] = 0.f;
        #pragma unroll
        for (int ks = 0; ks < 4; ++ks) {
            const int kk = kw + ks * 16;
            unsigned ah[2][4], al[2][4];
            #pragma unroll
            for (int mt = 0; mt < 2; ++mt) {
                int row = mt * 16 + a_row;
                unsigned aoff = (unsigned)row * 1024u +
                    ((((unsigned)(kk + a_kof) >> 3) ^ (unsigned)(row & 7)) << 4);
                ldsm_x4(ah[mt], sb + HH_OFF + aoff);
                ldsm_x4(al[mt], sb + HL_OFF + aoff);
            }
            #pragma unroll
            for (int mt = 0; mt < 2; ++mt)
                #pragma unroll
                for (int nt = 0; nt < 2; ++nt) {
                    mma_bf16(lacc[mt][nt], ah[mt], vfh[ks][nt]);
                    mma_bf16(lacc[mt][nt], al[mt], vfh[ks][nt]);
                    mma_bf16(lacc[mt][nt], ah[mt], vfl[ks][nt]);
                }
        }
        // RED2 store (stride 18 floats per row)
        {
            int g = l >> 2, q = l & 3;
            #pragma unroll
            for (int mt = 0; mt < 2; ++mt)
                #pragma unroll
                for (int nt = 0; nt < 2; ++nt) {
                    int m = mt * 16 + g, o = nt * 8 + 2 * q;
                    RED2[(w * 32 + m) * 18 + o]         = lacc[mt][nt][0];
                    RED2[(w * 32 + m) * 18 + o + 1]     = lacc[mt][nt][1];
                    RED2[(w * 32 + m + 8) * 18 + o]     = lacc[mt][nt][2];
                    RED2[(w * 32 + m + 8) * 18 + o + 1] = lacc[mt][nt][3];
                }
        }
        __syncthreads();
        float s0 = byv2.x, s1 = byv2.y;
        #pragma unroll
        for (int ww = 0; ww < 8; ++ww) {
            float2 p = *(const float2*)&RED2[(ww * 32 + lb) * 18 + lo2];
            s0 += p.x; s1 += p.y;
        }
        *(float2*)&out[((size_t)tprev * B_ + c0 + lb) * O_ + rr * 16 + lo2] =
            make_float2(s0, s1);
    };

    for (int t = 0; t < T_; ++t) {
        // prefetch U gather BEFORE the flag wait (no h dependency)
        int x = inp[t * B_ + c0 + en];
        float4 uv = *(const float4*)&g_Ut[(size_t)x * H_ + r0 + em];

        float acc[2][4][4];
        #pragma unroll
        for (int mt = 0; mt < 2; ++mt)
            #pragma unroll
            for (int nt = 0; nt < 4; ++nt)
                #pragma unroll
                for (int q = 0; q < 4; ++q) acc[mt][nt][q] = 0.f;

        // per-warp fused wait for BOTH producers of this k-slice (t>0)
        if (t > 0) {
            unsigned v0, v1;
            do {
                asm volatile("ld.acquire.gpu.u32 %0, [%1];" : "=r"(v0) : "l"(fl0) : "memory");
                asm volatile("ld.acquire.gpu.u32 %0, [%1];" : "=r"(v1) : "l"(fl1) : "memory");
            } while (v0 < (unsigned)t || v1 < (unsigned)t);
        }

        // per-warp fill of own k-slice (32 batch rows x 64 k), hi+lo
        {
            const unsigned short* sHi =
                (t == 0) ? g_h0hi : g_Hhi + (size_t)(t - 1) * B_ * H_;
            const unsigned short* sLo =
                (t == 0) ? g_h0lo : g_Hlo + (size_t)(t - 1) * B_ * H_;
            #pragma unroll
            for (int j = 0; j < 8; ++j) {
                int i = l + j * 32;
                int row = i >> 3;
                int cc = 8 * w + (i & 7);
                unsigned d = (unsigned)row * 1024u +
                             ((unsigned)(cc ^ (row & 7)) << 4);
                size_t src = (size_t)(c0 + row) * H_ + cc * 8;
                cp16(sb + HH_OFF + d, sHi + src);
                cp16(sb + HL_OFF + d, sLo + src);
            }
            cp_commit();
        }

        cp_wait<0>();
        __syncwarp();

        // single-pass 3-term recurrence: Wh*hh + Wl*hh + Wh*hl
        #pragma unroll
        for (int ks = 0; ks < 4; ++ks) {
            const int kk = kw + ks * 16;
            unsigned bhh[4][2], bhl[4][2];
            #pragma unroll
            for (int nt = 0; nt < 4; ++nt) {
                int rn = nt * 8 + b_i;
                unsigned base = (unsigned)rn * 1024u +
                    ((((unsigned)(kk + b_half * 8) >> 3) ^ (unsigned)(rn & 7)) << 4);
                ldsm_x2(bhh[nt], sb + HH_OFF + base);
                ldsm_x2(bhl[nt], sb + HL_OFF + base);
            }
            #pragma unroll
            for (int mt = 0; mt < 2; ++mt)
                #pragma unroll
                for (int nt = 0; nt < 4; ++nt) {
                    mma_bf16(acc[mt][nt], wfh[ks][mt], bhh[nt]);
                    mma_bf16(acc[mt][nt], wfl[ks][mt], bhh[nt]);
                    mma_bf16(acc[mt][nt], wfh[ks][mt], bhl[nt]);
                }
        }

        // cross-warp k reduction (8 partials)
        {
            int g = l >> 2, q = l & 3;
            #pragma unroll
            for (int mt = 0; mt < 2; ++mt)
                #pragma unroll
                for (int nt = 0; nt < 4; ++nt) {
                    int m = mt * 16 + g, n = nt * 8 + 2 * q;
                    RED[(w * 32 + m) * 33 + n]         = acc[mt][nt][0];
                    RED[(w * 32 + m) * 33 + n + 1]     = acc[mt][nt][1];
                    RED[(w * 32 + m + 8) * 33 + n]     = acc[mt][nt][2];
                    RED[(w * 32 + m + 8) * 33 + n + 1] = acc[mt][nt][3];
                }
        }
        __syncthreads();

        // epilogue: sum 8 partials + U + bias, tanh, store planes
        unsigned short* pHi = g_Hhi + (size_t)t * B_ * H_;
        unsigned short* pLo = g_Hlo + (size_t)t * B_ * H_;
        unsigned short hu[4], lu[4];
        const float* uvp = &uv.x;
        const float* bhp = &bhv.x;
        #pragma unroll
        for (int r = 0; r < 4; ++r) {
            int m = em + r;
            float s = 0.f;
            #pragma unroll
            for (int ww = 0; ww < 8; ++ww)
                s += RED[(ww * 32 + m) * 33 + en];
            float hv = fast_tanh(s + uvp[r] + bhp[r]);
            __nv_bfloat16 hi = __float2bfloat16_rn(hv);
            __nv_bfloat16 lo = __float2bfloat16_rn(hv - __bfloat162float(hi));
            hu[r] = __bfloat16_as_ushort(hi);
            lu[r] = __bfloat16_as_ushort(lo);
        }
        size_t ofs = (size_t)(c0 + en) * H_ + r0 + em;
        *(uint2*)&pHi[ofs] = *(uint2*)&hu[0];
        *(uint2*)&pLo[ofs] = *(uint2*)&lu[0];

        __syncthreads();
        // publish h_t (single-writer release)
        if (tid == 0) {
            asm volatile("st.release.gpu.u32 [%0], %1;"
                         :: "l"(myflag), "r"((unsigned)(t + 1)) : "memory");
        }

        // logits for h_{t-1} (still in smem), absorbed into spin slack
        if (t > 0) do_logits(t - 1);
    }

    // final pass: fill h_{T-1} and emit its logits
    {
        unsigned v0, v1;
        do {
            asm volatile("ld.acquire.gpu.u32 %0, [%1];" : "=r"(v0) : "l"(fl0) : "memory");
            asm volatile("ld.acquire.gpu.u32 %0, [%1];" : "=r"(v1) : "l"(fl1) : "memory");
        } while (v0 < (unsigned)T_ || v1 < (unsigned)T_);

        const unsigned short* sHi = g_Hhi + (size_t)(T_ - 1) * B_ * H_;
        const unsigned short* sLo = g_Hlo + (size_t)(T_ - 1) * B_ * H_;
        #pragma unroll
        for (int j = 0; j < 8; ++j) {
            int i = l + j * 32;
            int row = i >> 3;
            int cc = 8 * w + (i & 7);
            unsigned d = (unsigned)row * 1024u + ((unsigned)(cc ^ (row & 7)) << 4);
            size_t src = (size_t)(c0 + row) * H_ + cc * 8;
            cp16(sb + HH_OFF + d, sHi + src);
            cp16(sb + HL_OFF + d, sLo + src);
        }
        cp_commit();
        cp_wait<0>();
        __syncwarp();
        do_logits(T_ - 1);
    }

    // tail: ensure all consumers in this column group are done, reset flag
    group_barrier(bc);
    if (tid == 0)
        asm volatile("st.relaxed.gpu.u32 [%0], %1;" :: "l"(myflag), "r"(0u) : "memory");
}

// Optional hT (H,B) appended after logits: reconstruct from planes
__global__ void copy_hT_kernel(float* __restrict__ out) {
    int h = blockIdx.x;
    int b = threadIdx.x;
    size_t ofs = (size_t)(T_ - 1) * B_ * H_ + (size_t)b * H_ + h;
    out[(size_t)h * B_ + b] = bf16hl(g_Hhi[ofs]) + bf16hl(g_Hlo[ofs]);
}

extern "C" void kernel_launch(void* const* d_in, const int* in_sizes, int n_in,
                              void* d_out, int out_size) {
    const int*   inp = (const int*)d_in[0];
    const float* h0  = (const float*)d_in[1];
    const float* U   = (const float*)d_in[2];
    const float* W   = (const float*)d_in[3];
    const float* Vm  = (const float*)d_in[4];
    const float* bh  = (const float*)d_in[5];
    const float* by  = (const float*)d_in[6];
    float* out = (float*)d_out;

    cudaFuncSetAttribute(rnn_recur_mma,
                         cudaFuncAttributeMaxDynamicSharedMemorySize,
                         (int)SMEM_A_BYTES);

    prep_Ut<<<D_, H_>>>(U);
    prep_h0planes<<<B_, H_>>>(h0);
    prep_Vplanes<<<O_, H_>>>(Vm);

    rnn_recur_mma<<<NBLK_A, 256, SMEM_A_BYTES>>>(inp, W, bh, by, out);

    if (out_size >= T_ * B_ * O_ + H_ * B_) {
        copy_hT_kernel<<<H_, B_>>>(out + (size_t)T_ * B_ * O_);
    }
}

// round 17
// speedup vs baseline: 1.2856x; 1.1599x over previous
#include <cuda_runtime.h>
#include <cuda_bf16.h>
#include <math.h>
#include <stdint.h>

// Problem dims
#define T_ 1024
#define B_ 256
#define D_ 256
#define H_ 512
#define O_ 256

#define NBLK_A 128
#define MB 32
#define NB 32

typedef unsigned long long ull;

// bf16 hi/lo planes of hidden history, (t, b, h) layout, h contiguous
__device__ unsigned short g_Hhi[(size_t)T_ * B_ * H_];
__device__ unsigned short g_Hlo[(size_t)T_ * B_ * H_];
__device__ unsigned short g_h0hi[B_ * H_];
__device__ unsigned short g_h0lo[B_ * H_];
__device__ unsigned short g_Vhi[O_ * H_];
__device__ unsigned short g_Vlo[O_ * H_];
__device__ float          g_Ut[D_ * H_];      // U transposed (D, H)

// Per-(rowCTA, colgroup) producer flags, one cache line each. Single writer;
// value = t+1 after step t. Reset at tail -> replay-safe.
__device__ unsigned g_flag[16 * 8 * 32];
// Gen-based group barrier for the tail cleanup (monotone across replays)
__device__ unsigned g_cg_cnt[8 * 32];
__device__ unsigned g_cg_gen[8 * 32];

// ---------------- helpers ----------------
__device__ __forceinline__ float bf16hl(unsigned short u) {
    return __uint_as_float((unsigned)u << 16);
}
__device__ __forceinline__ unsigned smem_u32(const void* p) {
    return (unsigned)__cvta_generic_to_shared(p);
}
__device__ __forceinline__ void cp16(unsigned dst, const void* src) {
    asm volatile("cp.async.cg.shared.global [%0], [%1], 16;\n" ::"r"(dst), "l"(src));
}
__device__ __forceinline__ void cp_commit() {
    asm volatile("cp.async.commit_group;\n");
}
template <int N> __device__ __forceinline__ void cp_wait() {
    asm volatile("cp.async.wait_group %0;\n" ::"n"(N));
}
__device__ __forceinline__ float fast_tanh(float x) {
    float e, r;
    asm("ex2.approx.f32 %0, %1;" : "=f"(e) : "f"(x * 2.8853900817779268f));
    asm("rcp.approx.f32 %0, %1;" : "=f"(r) : "f"(e + 1.0f));
    return fmaf(-2.0f, r, 1.0f);
}
__device__ __forceinline__ void ldsm_x4(unsigned* r, unsigned addr) {
    asm volatile("ldmatrix.sync.aligned.m8n8.x4.shared.b16 {%0,%1,%2,%3}, [%4];"
                 : "=r"(r[0]), "=r"(r[1]), "=r"(r[2]), "=r"(r[3]) : "r"(addr));
}
__device__ __forceinline__ void ldsm_x2(unsigned* r, unsigned addr) {
    asm volatile("ldmatrix.sync.aligned.m8n8.x2.shared.b16 {%0,%1}, [%2];"
                 : "=r"(r[0]), "=r"(r[1]) : "r"(addr));
}
__device__ __forceinline__ void mma_bf16(float* d, const unsigned* a, const unsigned* b) {
    asm volatile(
        "mma.sync.aligned.m16n8k16.row.col.f32.bf16.bf16.f32 "
        "{%0,%1,%2,%3}, {%4,%5,%6,%7}, {%8,%9}, {%0,%1,%2,%3};"
        : "+f"(d[0]), "+f"(d[1]), "+f"(d[2]), "+f"(d[3])
        : "r"(a[0]), "r"(a[1]), "r"(a[2]), "r"(a[3]), "r"(b[0]), "r"(b[1]));
}

// Tail-only group barrier (16 arrivals), gen-based, replay-safe.
__device__ __forceinline__ void group_barrier(int bc) {
    __syncthreads();
    if (threadIdx.x == 0) {
        unsigned* cnt = &g_cg_cnt[bc * 32];
        unsigned* gen = &g_cg_gen[bc * 32];
        unsigned my;
        asm volatile("ld.relaxed.gpu.u32 %0, [%1];" : "=r"(my) : "l"(gen) : "memory");
        unsigned old;
        asm volatile("atom.add.release.gpu.u32 %0, [%1], %2;"
                     : "=r"(old) : "l"(cnt), "r"(1u) : "memory");
        if (old == 15u) {
            asm volatile("st.relaxed.gpu.u32 [%0], %1;" :: "l"(cnt), "r"(0u) : "memory");
            asm volatile("st.release.gpu.u32 [%0], %1;" :: "l"(gen), "r"(my + 1u) : "memory");
        } else {
            unsigned g;
            do {
                asm volatile("ld.acquire.gpu.u32 %0, [%1];" : "=r"(g) : "l"(gen) : "memory");
            } while (g == my);
        }
    }
    __syncthreads();
}

// ---------------- prep kernels ----------------
__global__ void prep_Ut(const float* __restrict__ U) {
    int d = blockIdx.x, h = threadIdx.x;
    g_Ut[(size_t)d * H_ + h] = U[(size_t)h * D_ + d];
}
__global__ void prep_h0planes(const float* __restrict__ h0) {
    int b = blockIdx.x, h = threadIdx.x;
    float v = h0[(size_t)h * B_ + b];
    __nv_bfloat16 hi = __float2bfloat16_rn(v);
    __nv_bfloat16 lo = __float2bfloat16_rn(v - __bfloat162float(hi));
    g_h0hi[(size_t)b * H_ + h] = __bfloat16_as_ushort(hi);
    g_h0lo[(size_t)b * H_ + h] = __bfloat16_as_ushort(lo);
}
__global__ void prep_Vplanes(const float* __restrict__ Vm) {
    int o = blockIdx.x, h = threadIdx.x;
    float v = Vm[(size_t)o * H_ + h];
    __nv_bfloat16 hi = __float2bfloat16_rn(v);
    __nv_bfloat16 lo = __float2bfloat16_rn(v - __bfloat162float(hi));
    g_Vhi[(size_t)o * H_ + h] = __bfloat16_as_ushort(hi);
    g_Vlo[(size_t)o * H_ + h] = __bfloat16_as_ushort(lo);
}

// ------- Fused recurrence + logits, tail overlapped into fill shadow -------
#define WH_OFF 0
#define WL_OFF 32768
#define HH_OFF 65536
#define HL_OFF 98304
#define RED_OFF 131072
#define REDSZ   (8 * 32 * 33 * 4)               // 33792
#define RED2_OFF (RED_OFF + REDSZ)              // 164864
#define RED2SZ  (8 * 32 * 18 * 4)               // 18432 per parity buffer
#define SMEM_A_BYTES (RED2_OFF + 2 * RED2SZ)    // 201728

__global__ void __launch_bounds__(256, 1)
rnn_recur_mma(const int* __restrict__ inp, const float* __restrict__ W,
              const float* __restrict__ bh, const float* __restrict__ by,
              float* __restrict__ out)
{
    extern __shared__ char smem[];
    const unsigned sb = smem_u32(smem);
    float* RED = (float*)(smem + RED_OFF);

    const int tid = threadIdx.x;
    const int w   = tid >> 5;           // 8 warps, k-split 8 x 64
    const int l   = tid & 31;
    const int bid = blockIdx.x;
    const int rr  = bid >> 3;           // row-CTA index (0..15)
    const int r0  = rr * MB;
    const int bc  = bid & 7;
    const int c0  = bc * NB;

    // one-time: split W slab (32 x 512) into Wh/Wl bf16, swizzled smem
    for (int i = tid; i < MB * H_; i += 256) {
        int row = i >> 9, k = i & 511;
        float wv = W[(size_t)(r0 + row) * H_ + k];
        __nv_bfloat16 hi = __float2bfloat16_rn(wv);
        __nv_bfloat16 lo = __float2bfloat16_rn(wv - __bfloat162float(hi));
        unsigned off = (unsigned)row * 1024u +
                       ((((unsigned)k >> 3) ^ (unsigned)(row & 7)) << 4) +
                       (unsigned)(k & 7) * 2u;
        *(__nv_bfloat16*)(smem + WH_OFF + off) = hi;
        *(__nv_bfloat16*)(smem + WL_OFF + off) = lo;
    }

    // recurrence epilogue ownership: col en (0..31), rows em..em+3
    const int en = tid >> 3;
    const int em = (tid & 7) * 4;
    const float4 bhv = *(const float4*)&bh[r0 + em];
    // logits epilogue ownership: batch lb (0..31), o pair lo2
    const int lb  = tid >> 3;
    const int lo2 = (tid & 7) * 2;
    const float2 byv2 = *(const float2*)&by[rr * 16 + lo2];

    // stage V slice (16 o-rows x 512 k, hi/lo) into RED area, swizzled
    for (int i = tid; i < 16 * 64; i += 256) {
        int row = i >> 6, c = i & 63;
        unsigned d = (unsigned)row * 1024u + ((unsigned)(c ^ (row & 7)) << 4);
        size_t src = (size_t)(rr * 16 + row) * H_ + c * 8;
        cp16(sb + RED_OFF + d,         g_Vhi + src);
        cp16(sb + RED_OFF + 16384 + d, g_Vlo + src);
    }
    cp_commit();
    cp_wait<0>();
    __syncthreads();

    // ldmatrix lane geometry (warp owns 64-wide k slice)
    const int kw    = w * 64;
    const int quad  = l >> 3, li = l & 7;
    const int a_row = ((quad & 1) << 3) + li;
    const int a_kof = (quad >> 1) << 3;
    const int b_i   = l & 7;
    const int b_half = (l >> 3) & 1;

    // hoist V fragments (B operand: 16 o-rows, own k slice) -> 32 regs
    unsigned vfh[4][2][2], vfl[4][2][2];
    #pragma unroll
    for (int ks = 0; ks < 4; ++ks) {
        const int kk = kw + ks * 16;
        #pragma unroll
        for (int nt = 0; nt < 2; ++nt) {
            int rn = nt * 8 + b_i;
            unsigned off = (unsigned)rn * 1024u +
                ((((unsigned)(kk + b_half * 8) >> 3) ^ (unsigned)(rn & 7)) << 4);
            ldsm_x2(vfh[ks][nt], sb + RED_OFF + off);
            ldsm_x2(vfl[ks][nt], sb + RED_OFF + 16384 + off);
        }
    }
    __syncthreads();   // V staging area reverts to RED scratch

    // hoist W fragments -> 64 regs
    unsigned wfh[4][2][4], wfl[4][2][4];
    #pragma unroll
    for (int ks = 0; ks < 4; ++ks) {
        const int kk = kw + ks * 16;
        #pragma unroll
        for (int mt = 0; mt < 2; ++mt) {
            int row = mt * 16 + a_row;
            unsigned aoff = (unsigned)row * 1024u +
                ((((unsigned)(kk + a_kof) >> 3) ^ (unsigned)(row & 7)) << 4);
            ldsm_x4(wfh[ks][mt], sb + WH_OFF + aoff);
            ldsm_x4(wfl[ks][mt], sb + WL_OFF + aoff);
        }
    }

    const unsigned* fl0 = &g_flag[((2 * w)     * 8 + bc) * 32];
    const unsigned* fl1 = &g_flag[((2 * w + 1) * 8 + bc) * 32];
    unsigned* myflag = &g_flag[(rr * 8 + bc) * 32];

    // logits MMA for the h currently in smem; partials stay in registers
    auto logits_mma = [&](float (&lacc)[2][2][4]) {
        #pragma unroll
        for (int mt = 0; mt < 2; ++mt)
            #pragma unroll
            for (int nt = 0; nt < 2; ++nt)
                #pragma unroll
                for (int q = 0; q < 4; ++q) lacc[mt][nt][q] = 0.f;
        #pragma unroll
        for (int ks = 0; ks < 4; ++ks) {
            const int kk = kw + ks * 16;
            unsigned ah[2][4], al[2][4];
            #pragma unroll
            for (int mt = 0; mt < 2; ++mt) {
                int row = mt * 16 + a_row;
                unsigned aoff = (unsigned)row * 1024u +
                    ((((unsigned)(kk + a_kof) >> 3) ^ (unsigned)(row & 7)) << 4);
                ldsm_x4(ah[mt], sb + HH_OFF + aoff);
                ldsm_x4(al[mt], sb + HL_OFF + aoff);
            }
            #pragma unroll
            for (int mt = 0; mt < 2; ++mt)
                #pragma unroll
                for (int nt = 0; nt < 2; ++nt) {
                    mma_bf16(lacc[mt][nt], ah[mt], vfh[ks][nt]);
                    mma_bf16(lacc[mt][nt], al[mt], vfh[ks][nt]);
                    mma_bf16(lacc[mt][nt], ah[mt], vfl[ks][nt]);
                }
        }
    };

    // logits tail: RED2[par] exchange + reduce + STG out[tprev]
    auto logits_tail = [&](float (&lacc)[2][2][4], int tprev, int par) {
        float* RED2 = (float*)(smem + RED2_OFF + par * RED2SZ);
        {
            int g = l >> 2, q = l & 3;
            #pragma unroll
            for (int mt = 0; mt < 2; ++mt)
                #pragma unroll
                for (int nt = 0; nt < 2; ++nt) {
                    int m = mt * 16 + g, o = nt * 8 + 2 * q;
                    RED2[(w * 32 + m) * 18 + o]         = lacc[mt][nt][0];
                    RED2[(w * 32 + m) * 18 + o + 1]     = lacc[mt][nt][1];
                    RED2[(w * 32 + m + 8) * 18 + o]     = lacc[mt][nt][2];
                    RED2[(w * 32 + m + 8) * 18 + o + 1] = lacc[mt][nt][3];
                }
        }
        __syncthreads();
        float s0 = byv2.x, s1 = byv2.y;
        #pragma unroll
        for (int ww = 0; ww < 8; ++ww) {
            float2 p = *(const float2*)&RED2[(ww * 32 + lb) * 18 + lo2];
            s0 += p.x; s1 += p.y;
        }
        *(float2*)&out[((size_t)tprev * B_ + c0 + lb) * O_ + rr * 16 + lo2] =
            make_float2(s0, s1);
    };

    float lacc[2][2][4];   // logits partials carried across iterations

    for (int t = 0; t < T_; ++t) {
        // prefetch U gather BEFORE the flag wait (no h dependency)
        int x = inp[t * B_ + c0 + en];
        float4 uv = *(const float4*)&g_Ut[(size_t)x * H_ + r0 + em];

        // relaxed poll for BOTH producers, then one acquire confirm each
        if (t > 0) {
            unsigned v0, v1;
            do {
                asm volatile("ld.relaxed.gpu.u32 %0, [%1];" : "=r"(v0) : "l"(fl0) : "memory");
                asm volatile("ld.relaxed.gpu.u32 %0, [%1];" : "=r"(v1) : "l"(fl1) : "memory");
            } while (v0 < (unsigned)t || v1 < (unsigned)t);
            asm volatile("ld.acquire.gpu.u32 %0, [%1];" : "=r"(v0) : "l"(fl0) : "memory");
            asm volatile("ld.acquire.gpu.u32 %0, [%1];" : "=r"(v1) : "l"(fl1) : "memory");
        }

        // issue per-warp fill of own k-slice (32 batch rows x 64 k), hi+lo
        {
            const unsigned short* sHi =
                (t == 0) ? g_h0hi : g_Hhi + (size_t)(t - 1) * B_ * H_;
            const unsigned short* sLo =
                (t == 0) ? g_h0lo : g_Hlo + (size_t)(t - 1) * B_ * H_;
            #pragma unroll
            for (int j = 0; j < 8; ++j) {
                int i = l + j * 32;
                int row = i >> 3;
                int cc = 8 * w + (i & 7);
                unsigned d = (unsigned)row * 1024u +
                             ((unsigned)(cc ^ (row & 7)) << 4);
                size_t src = (size_t)(c0 + row) * H_ + cc * 8;
                cp16(sb + HH_OFF + d, sHi + src);
                cp16(sb + HL_OFF + d, sLo + src);
            }
            cp_commit();
        }

        // logits tail for out[t-2] runs inside the fill's L2 shadow
        if (t >= 2) logits_tail(lacc, t - 2, t & 1);

        float acc[2][4][4];
        #pragma unroll
        for (int mt = 0; mt < 2; ++mt)
            #pragma unroll
            for (int nt = 0; nt < 4; ++nt)
                #pragma unroll
                for (int q = 0; q < 4; ++q) acc[mt][nt][q] = 0.f;

        cp_wait<0>();
        __syncwarp();

        // single-pass 3-term recurrence: Wh*hh + Wl*hh + Wh*hl
        #pragma unroll
        for (int ks = 0; ks < 4; ++ks) {
            const int kk = kw + ks * 16;
            unsigned bhh[4][2], bhl[4][2];
            #pragma unroll
            for (int nt = 0; nt < 4; ++nt) {
                int rn = nt * 8 + b_i;
                unsigned base = (unsigned)rn * 1024u +
                    ((((unsigned)(kk + b_half * 8) >> 3) ^ (unsigned)(rn & 7)) << 4);
                ldsm_x2(bhh[nt], sb + HH_OFF + base);
                ldsm_x2(bhl[nt], sb + HL_OFF + base);
            }
            #pragma unroll
            for (int mt = 0; mt < 2; ++mt)
                #pragma unroll
                for (int nt = 0; nt < 4; ++nt) {
                    mma_bf16(acc[mt][nt], wfh[ks][mt], bhh[nt]);
                    mma_bf16(acc[mt][nt], wfl[ks][mt], bhh[nt]);
                    mma_bf16(acc[mt][nt], wfh[ks][mt], bhl[nt]);
                }
        }

        // cross-warp k reduction (8 partials)
        {
            int g = l >> 2, q = l & 3;
            #pragma unroll
            for (int mt = 0; mt < 2; ++mt)
                #pragma unroll
                for (int nt = 0; nt < 4; ++nt) {
                    int m = mt * 16 + g, n = nt * 8 + 2 * q;
                    RED[(w * 32 + m) * 33 + n]         = acc[mt][nt][0];
                    RED[(w * 32 + m) * 33 + n + 1]     = acc[mt][nt][1];
                    RED[(w * 32 + m + 8) * 33 + n]     = acc[mt][nt][2];
                    RED[(w * 32 + m + 8) * 33 + n + 1] = acc[mt][nt][3];
                }
        }
        __syncthreads();

        // epilogue: sum 8 partials + U + bias, tanh, store planes
        unsigned short* pHi = g_Hhi + (size_t)t * B_ * H_;
        unsigned short* pLo = g_Hlo + (size_t)t * B_ * H_;
        unsigned short hu[4], lu[4];
        const float* uvp = &uv.x;
        const float* bhp = &bhv.x;
        #pragma unroll
        for (int r = 0; r < 4; ++r) {
            int m = em + r;
            float s = 0.f;
            #pragma unroll
            for (int ww = 0; ww < 8; ++ww)
                s += RED[(ww * 32 + m) * 33 + en];
            float hv = fast_tanh(s + uvp[r] + bhp[r]);
            __nv_bfloat16 hi = __float2bfloat16_rn(hv);
            __nv_bfloat16 lo = __float2bfloat16_rn(hv - __bfloat162float(hi));
            hu[r] = __bfloat16_as_ushort(hi);
            lu[r] = __bfloat16_as_ushort(lo);
        }
        size_t ofs = (size_t)(c0 + en) * H_ + r0 + em;
        *(uint2*)&pHi[ofs] = *(uint2*)&hu[0];
        *(uint2*)&pLo[ofs] = *(uint2*)&lu[0];

        __syncthreads();
        // publish h_t (single-writer release)
        if (tid == 0) {
            asm volatile("st.release.gpu.u32 [%0], %1;"
                         :: "l"(myflag), "r"((unsigned)(t + 1)) : "memory");
        }

        // logits MMA for h_{t-1} (still in smem); tail deferred to next iter
        if (t > 0) logits_mma(lacc);
    }

    // flush: tail for out[T-2]
    logits_tail(lacc, T_ - 2, 0);

    // final pass: fill h_{T-1}, compute + emit out[T-1]
    {
        unsigned v0, v1;
        do {
            asm volatile("ld.relaxed.gpu.u32 %0, [%1];" : "=r"(v0) : "l"(fl0) : "memory");
            asm volatile("ld.relaxed.gpu.u32 %0, [%1];" : "=r"(v1) : "l"(fl1) : "memory");
        } while (v0 < (unsigned)T_ || v1 < (unsigned)T_);
        asm volatile("ld.acquire.gpu.u32 %0, [%1];" : "=r"(v0) : "l"(fl0) : "memory");
        asm volatile("ld.acquire.gpu.u32 %0, [%1];" : "=r"(v1) : "l"(fl1) : "memory");

        const unsigned short* sHi = g_Hhi + (size_t)(T_ - 1) * B_ * H_;
        const unsigned short* sLo = g_Hlo + (size_t)(T_ - 1) * B_ * H_;
        #pragma unroll
        for (int j = 0; j < 8; ++j) {
            int i = l + j * 32;
            int row = i >> 3;
            int cc = 8 * w + (i & 7);
            unsigned d = (unsigned)row * 1024u + ((unsigned)(cc ^ (row & 7)) << 4);
            size_t src = (size_t)(c0 + row) * H_ + cc * 8;
            cp16(sb + HH_OFF + d, sHi + src);
            cp16(sb + HL_OFF + d, sLo + src);
        }
        cp_commit();
        cp_wait<0>();
        __syncwarp();
        logits_mma(lacc);
        __syncthreads();
        logits_tail(lacc, T_ - 1, 1);
    }

    // tail: ensure all consumers in this column group are done, reset flag
    group_barrier(bc);
    if (tid == 0)
        asm volatile("st.relaxed.gpu.u32 [%0], %1;" :: "l"(myflag), "r"(0u) : "memory");
}

// Optional hT (H,B) appended after logits: reconstruct from planes
__global__ void copy_hT_kernel(float* __restrict__ out) {
    int h = blockIdx.x;
    int b = threadIdx.x;
    size_t ofs = (size_t)(T_ - 1) * B_ * H_ + (size_t)b * H_ + h;
    out[(size_t)h * B_ + b] = bf16hl(g_Hhi[ofs]) + bf16hl(g_Hlo[ofs]);
}

extern "C" void kernel_launch(void* const* d_in, const int* in_sizes, int n_in,
                              void* d_out, int out_size) {
    const int*   inp = (const int*)d_in[0];
    const float* h0  = (const float*)d_in[1];
    const float* U   = (const float*)d_in[2];
    const float* W   = (const float*)d_in[3];
    const float* Vm  = (const float*)d_in[4];
    const float* bh  = (const float*)d_in[5];
    const float* by  = (const float*)d_in[6];
    float* out = (float*)d_out;

    cudaFuncSetAttribute(rnn_recur_mma,
                         cudaFuncAttributeMaxDynamicSharedMemorySize,
                         (int)SMEM_A_BYTES);

    prep_Ut<<<D_, H_>>>(U);
    prep_h0planes<<<B_, H_>>>(h0);
    prep_Vplanes<<<O_, H_>>>(Vm);

    rnn_recur_mma<<<NBLK_A, 256, SMEM_A_BYTES>>>(inp, W, bh, by, out);

    if (out_size >= T_ * B_ * O_ + H_ * B_) {
        copy_hT_kernel<<<H_, B_>>>(out + (size_t)T_ * B_ * O_);
    }
}